// round 12
// baseline (speedup 1.0000x reference)
#include <cuda_runtime.h>
#include <mma.h>
#include <cstdint>

using namespace nvcuda;

#define NB     16
#define DMODEL 512
#define NPOS   1024
#define NHEAD  8
#define DK     64

// ---------------- static device scratch (no allocations allowed) ----------------
__device__ float gQ[NB*NHEAD*NPOS*DK];   // 33.5 MB  [b,h,n,dk]
__device__ float gK[NB*NHEAD*NPOS*DK];
__device__ float gV[NB*NHEAD*NPOS*DK];
__device__ float gO[NB*DMODEL*NPOS];     // attention out, image layout
__device__ float gZ[NB*DMODEL*NPOS];     // post Wo+InstanceNorm

// Split a loaded fp32 fragment into tf32 hi + tf32 lo (3xTF32 trick).
template <typename FragT>
__device__ __forceinline__ void split_frag(FragT& hi, FragT& lo) {
#pragma unroll
    for (int t = 0; t < hi.num_elements; t++) {
        float v = hi.x[t];
        float h = wmma::__float_to_tf32(v);
        hi.x[t] = h;
        lo.x[t] = wmma::__float_to_tf32(v - h);
    }
}

// =====================================================================
// GEMM: out(512x1024 per batch) = W(512x512) @ X(512x1024) + bias
// 3xTF32 compensated. epi==1: QKV gather epilogue to [b,h,n,dk] with
// h=(p%512)/64, n=2*o+(p>>9), dk=p%64.
// tiles: BM=64, BN=128, BK=32, 256 threads, wmma tf32 m16n16k8
// =====================================================================
__global__ __launch_bounds__(256) void gemm_k(
    const float* __restrict__ X, const float* __restrict__ W,
    const float* __restrict__ bias, float* __restrict__ out, int epi)
{
    __shared__ __align__(16) float sbuf[64*136];   // 34.8 KB, reused for epilogue
    float* As = sbuf;            // [64][40]
    float* Bs = sbuf + 64*40;    // [32][136]

    const int b  = blockIdx.z;
    const int m0 = blockIdx.y * 64;
    const int n0 = blockIdx.x * 128;
    const float* Xb = X + (size_t)b * DMODEL * NPOS;
    const int tid = threadIdx.x;
    const int wid = tid >> 5;
    const int wm  = wid & 1;     // 2 stripes of 32 rows
    const int wn  = wid >> 1;    // 4 stripes of 32 cols

    wmma::fragment<wmma::accumulator,16,16,8,float> c[2][2];
#pragma unroll
    for (int i=0;i<2;i++)
#pragma unroll
        for (int j=0;j<2;j++) wmma::fill_fragment(c[i][j], 0.0f);

    for (int k0 = 0; k0 < DMODEL; k0 += 32) {
#pragma unroll
        for (int i=0;i<2;i++){                       // A: 64x32 = 512 float4
            int idx = tid + i*256;
            int r = idx >> 3, c4 = idx & 7;
            *(float4*)(As + r*40 + c4*4) =
                *(const float4*)(W + (size_t)(m0+r)*DMODEL + k0 + c4*4);
        }
#pragma unroll
        for (int i=0;i<4;i++){                       // B: 32x128 = 1024 float4
            int idx = tid + i*256;
            int r = idx >> 5, c4 = idx & 31;
            *(float4*)(Bs + r*136 + c4*4) =
                *(const float4*)(Xb + (size_t)(k0+r)*NPOS + n0 + c4*4);
        }
        __syncthreads();
#pragma unroll
        for (int kk=0;kk<32;kk+=8){
            wmma::fragment<wmma::matrix_a,16,16,8,wmma::precision::tf32,wmma::row_major> ah[2], al[2];
            wmma::fragment<wmma::matrix_b,16,16,8,wmma::precision::tf32,wmma::row_major> bh[2], bl[2];
#pragma unroll
            for (int i=0;i<2;i++){
                wmma::load_matrix_sync(ah[i], As + (wm*32+i*16)*40 + kk, 40);
                split_frag(ah[i], al[i]);
            }
#pragma unroll
            for (int j=0;j<2;j++){
                wmma::load_matrix_sync(bh[j], Bs + kk*136 + wn*32 + j*16, 136);
                split_frag(bh[j], bl[j]);
            }
#pragma unroll
            for (int i=0;i<2;i++)
#pragma unroll
                for (int j=0;j<2;j++){
                    wmma::mma_sync(c[i][j], al[i], bh[j], c[i][j]);
                    wmma::mma_sync(c[i][j], ah[i], bl[j], c[i][j]);
                    wmma::mma_sync(c[i][j], ah[i], bh[j], c[i][j]);
                }
        }
        __syncthreads();
    }

    float* Cs = sbuf;   // [64][136]
#pragma unroll
    for (int i=0;i<2;i++)
#pragma unroll
        for (int j=0;j<2;j++)
            wmma::store_matrix_sync(Cs + (wm*32+i*16)*136 + wn*32 + j*16,
                                    c[i][j], 136, wmma::mem_row_major);
    __syncthreads();

    if (epi == 0) {
        float* ob = out + (size_t)b*DMODEL*NPOS;
        for (int idx = tid; idx < 64*128; idx += 256) {
            int r = idx >> 7, cc = idx & 127;
            int o = m0 + r, p = n0 + cc;
            ob[(size_t)o*NPOS + p] = Cs[r*136+cc] + bias[o];
        }
    } else {
        for (int idx = tid; idx < 64*128; idx += 256) {
            int r = idx >> 7, cc = idx & 127;
            int o = m0 + r, p = n0 + cc;
            int h  = (p & 511) >> 6;
            int n  = 2*o + (p >> 9);
            int dk = p & 63;
            out[(((size_t)b*NHEAD + h)*NPOS + n)*DK + dk] = Cs[r*136+cc] + bias[o];
        }
    }
}

// =====================================================================
// Fused attention: per block = 32 query rows of one (b,h).
//   1) S stripe (32 x 1024) = Q·K^T / 8 in smem (3xTF32 wmma),
//      streaming K in 128-row chunks.
//   2) softmax across the full 1024 row in smem (warp per row).
//   3) O (32 x 64) = P·V (3xTF32), streaming V in 128-row chunks.
//   4) epilogue scatters to image layout gO[b, h*64+dk, n].
// 256 threads. Dynamic smem: S 32x1032 + Q 32x72 + KV 128x72 = 174 KB.
// =====================================================================
#define S_LD   1032
#define QKV_LD 72
#define ATTN_SMEM_FLOATS (32*S_LD + 32*QKV_LD + 128*QKV_LD)

__global__ __launch_bounds__(256) void attn_kernel(
    const float* __restrict__ Q, const float* __restrict__ K,
    const float* __restrict__ V, float* __restrict__ O)
{
    extern __shared__ __align__(16) float smem[];
    float* Ss  = smem;                   // [32][1032]
    float* Qs  = smem + 32*S_LD;         // [32][72]
    float* KVs = Qs + 32*QKV_LD;         // [128][72]

    const int bh = blockIdx.y;
    const int b  = bh >> 3, h = bh & 7;
    const int m0 = blockIdx.x * 32;
    const int tid = threadIdx.x;
    const int wid = tid >> 5;
    const int lane = tid & 31;

    const float* Qb = Q + (size_t)bh*NPOS*DK;
    const float* Kb = K + (size_t)bh*NPOS*DK;
    const float* Vb = V + (size_t)bh*NPOS*DK;

    // ---- load Q tile (32 x 64 = 512 float4) ----
#pragma unroll
    for (int i=0;i<2;i++){
        int idx = tid + i*256;
        int r = idx >> 4, c4 = idx & 15;
        *(float4*)(Qs + r*QKV_LD + c4*4) =
            *(const float4*)(Qb + (size_t)(m0+r)*DK + c4*4);
    }
    __syncthreads();

    // ---- S stripe: loop over 8 key chunks of 128 ----
    const int wm = wid & 1;      // 2 stripes of 16 rows
    const int wn = wid >> 1;     // 4 stripes of 32 cols
    for (int kc = 0; kc < 8; kc++) {
#pragma unroll
        for (int i=0;i<8;i++){                    // K chunk: 128x64 = 2048 float4
            int idx = tid + i*256;
            int r = idx >> 4, c4 = idx & 15;
            *(float4*)(KVs + r*QKV_LD + c4*4) =
                *(const float4*)(Kb + (size_t)(kc*128+r)*DK + c4*4);
        }
        __syncthreads();

        wmma::fragment<wmma::accumulator,16,16,8,float> c[2];
        wmma::fill_fragment(c[0], 0.0f);
        wmma::fill_fragment(c[1], 0.0f);
#pragma unroll
        for (int kk=0;kk<64;kk+=8){
            wmma::fragment<wmma::matrix_a,16,16,8,wmma::precision::tf32,wmma::row_major> ah, al;
            wmma::load_matrix_sync(ah, Qs + (wm*16)*QKV_LD + kk, QKV_LD);
            split_frag(ah, al);
#pragma unroll
            for (int j=0;j<2;j++){
                wmma::fragment<wmma::matrix_b,16,16,8,wmma::precision::tf32,wmma::col_major> bh2, bl2;
                wmma::load_matrix_sync(bh2, KVs + (wn*32+j*16)*QKV_LD + kk, QKV_LD);
                split_frag(bh2, bl2);
                wmma::mma_sync(c[j], al, bh2, c[j]);
                wmma::mma_sync(c[j], ah, bl2, c[j]);
                wmma::mma_sync(c[j], ah, bh2, c[j]);
            }
        }
#pragma unroll
        for (int j=0;j<2;j++){
#pragma unroll
            for (int t=0;t<c[j].num_elements;t++) c[j].x[t] *= 0.125f;
            wmma::store_matrix_sync(Ss + (wm*16)*S_LD + kc*128 + wn*32 + j*16,
                                    c[j], S_LD, wmma::mem_row_major);
        }
        __syncthreads();   // S stores visible AND KVs free for next chunk
    }

    // ---- softmax across full 1024 row, warp per row, 4 rows per warp ----
#pragma unroll
    for (int it=0; it<4; it++){
        int r = it*8 + wid;
        float4* p = (float4*)(Ss + (size_t)r*S_LD);
        float4 v[8];
        float mx = -1e30f;
#pragma unroll
        for (int i=0;i<8;i++){
            v[i] = p[lane + 32*i];
            mx = fmaxf(mx, fmaxf(fmaxf(v[i].x, v[i].y), fmaxf(v[i].z, v[i].w)));
        }
#pragma unroll
        for (int s=16;s>0;s>>=1) mx = fmaxf(mx, __shfl_xor_sync(0xffffffffu, mx, s));
        float sum = 0.0f;
#pragma unroll
        for (int i=0;i<8;i++){
            v[i].x = __expf(v[i].x - mx); v[i].y = __expf(v[i].y - mx);
            v[i].z = __expf(v[i].z - mx); v[i].w = __expf(v[i].w - mx);
            sum += v[i].x + v[i].y + v[i].z + v[i].w;
        }
#pragma unroll
        for (int s=16;s>0;s>>=1) sum += __shfl_xor_sync(0xffffffffu, sum, s);
        float inv = 1.0f / sum;
#pragma unroll
        for (int i=0;i<8;i++){
            v[i].x *= inv; v[i].y *= inv; v[i].z *= inv; v[i].w *= inv;
            p[lane + 32*i] = v[i];
        }
    }
    __syncthreads();

    // ---- O = P·V : warp tile 16m x 16n; 2 (m) x 4 (n) warps cover 32x64 ----
    const int om = wid & 1;      // 2 stripes of 16 rows
    const int on = wid >> 1;     // 4 stripes of 16 dk cols
    wmma::fragment<wmma::accumulator,16,16,8,float> oacc;
    wmma::fill_fragment(oacc, 0.0f);
    for (int vc = 0; vc < 8; vc++) {
#pragma unroll
        for (int i=0;i<8;i++){                    // V chunk: 128x64
            int idx = tid + i*256;
            int r = idx >> 4, c4 = idx & 15;
            *(float4*)(KVs + r*QKV_LD + c4*4) =
                *(const float4*)(Vb + (size_t)(vc*128+r)*DK + c4*4);
        }
        __syncthreads();
#pragma unroll
        for (int kk=0;kk<128;kk+=8){
            wmma::fragment<wmma::matrix_a,16,16,8,wmma::precision::tf32,wmma::row_major> ah, al;
            wmma::load_matrix_sync(ah, Ss + (om*16)*S_LD + vc*128 + kk, S_LD);
            split_frag(ah, al);
            wmma::fragment<wmma::matrix_b,16,16,8,wmma::precision::tf32,wmma::row_major> bh2, bl2;
            wmma::load_matrix_sync(bh2, KVs + kk*QKV_LD + on*16, QKV_LD);
            split_frag(bh2, bl2);
            wmma::mma_sync(oacc, al, bh2, oacc);
            wmma::mma_sync(oacc, ah, bl2, oacc);
            wmma::mma_sync(oacc, ah, bh2, oacc);
        }
        __syncthreads();   // KVs free for next chunk
    }

    // ---- epilogue: stage col-major [dk][m] then coalesced image writes ----
    float* Cs = Ss;   // reuse
    wmma::store_matrix_sync(Cs + (on*16)*40 + om*16, oacc, 40, wmma::mem_col_major);
    __syncthreads();

    float* Ob = O + (size_t)b*DMODEL*NPOS;
    for (int idx = tid; idx < 64*32; idx += 256) {
        int dk = idx >> 5, mm = idx & 31;
        Ob[(size_t)(h*DK + dk)*NPOS + m0 + mm] = Cs[dk*40 + mm];
    }
}

// =====================================================================
// InstanceNorm (affine=False, biased var, eps=1e-5) in place.
// One warp per (b,c) row of 1024 spatial values; two-pass in registers.
// =====================================================================
__global__ __launch_bounds__(256) void inorm_kernel(float* __restrict__ Z)
{
    const int row  = blockIdx.x*8 + (threadIdx.x >> 5);
    const int lane = threadIdx.x & 31;
    float4* p = (float4*)(Z + (size_t)row*NPOS);
    float4 v[8];
    float s = 0.0f;
#pragma unroll
    for (int i=0;i<8;i++){ v[i] = p[lane + 32*i]; s += v[i].x+v[i].y+v[i].z+v[i].w; }
#pragma unroll
    for (int sh=16;sh>0;sh>>=1) s += __shfl_xor_sync(0xffffffffu, s, sh);
    const float mean = s * (1.0f/1024.0f);
    float q = 0.0f;
#pragma unroll
    for (int i=0;i<8;i++){
        float a=v[i].x-mean, b2=v[i].y-mean, c2=v[i].z-mean, d=v[i].w-mean;
        q += a*a + b2*b2 + c2*c2 + d*d;
    }
#pragma unroll
    for (int sh=16;sh>0;sh>>=1) q += __shfl_xor_sync(0xffffffffu, q, sh);
    const float inv = rsqrtf(q * (1.0f/1024.0f) + 1e-5f);
#pragma unroll
    for (int i=0;i<8;i++){
        v[i].x = (v[i].x-mean)*inv; v[i].y = (v[i].y-mean)*inv;
        v[i].z = (v[i].z-mean)*inv; v[i].w = (v[i].w-mean)*inv;
        p[lane + 32*i] = v[i];
    }
}

// =====================================================================
extern "C" void kernel_launch(void* const* d_in, const int* in_sizes, int n_in,
                              void* d_out, int out_size)
{
    (void)in_sizes; (void)n_in; (void)out_size;
    const float* x  = (const float*)d_in[0];
    const float* Wq = (const float*)d_in[1];
    const float* bq = (const float*)d_in[2];
    const float* Wk = (const float*)d_in[3];
    const float* bk = (const float*)d_in[4];
    const float* Wv = (const float*)d_in[5];
    const float* bv = (const float*)d_in[6];
    const float* Wo = (const float*)d_in[7];
    const float* bo = (const float*)d_in[8];
    float* out = (float*)d_out;

    float *pQ, *pK, *pV, *pO, *pZ;
    cudaGetSymbolAddress((void**)&pQ, gQ);
    cudaGetSymbolAddress((void**)&pK, gK);
    cudaGetSymbolAddress((void**)&pV, gV);
    cudaGetSymbolAddress((void**)&pO, gO);
    cudaGetSymbolAddress((void**)&pZ, gZ);

    const int attn_smem = ATTN_SMEM_FLOATS * (int)sizeof(float);   // 178,176 B
    cudaFuncSetAttribute(attn_kernel,
                         cudaFuncAttributeMaxDynamicSharedMemorySize, attn_smem);

    dim3 t(256);
    dim3 gGemm(8, 8, 16);          // n-tiles(1024/128), m-tiles(512/64), batch

    gemm_k<<<gGemm, t>>>(x, Wq, bq, pQ, 1);
    gemm_k<<<gGemm, t>>>(x, Wk, bk, pK, 1);
    gemm_k<<<gGemm, t>>>(x, Wv, bv, pV, 1);

    attn_kernel<<<dim3(32, 128), t, attn_smem>>>(pQ, pK, pV, pO);

    gemm_k<<<gGemm, t>>>(pO, Wo, bo, pZ, 0);
    inorm_kernel<<<1024, t>>>(pZ);             // 8192 rows / 8 per block
    gemm_k<<<gGemm, t>>>(pZ, Wo, bo, out, 0);
}

// round 14
// speedup vs baseline: 1.0031x; 1.0031x over previous
#include <cuda_runtime.h>
#include <mma.h>
#include <cstdint>

using namespace nvcuda;

#define NB     16
#define DMODEL 512
#define NPOS   1024
#define NHEAD  8
#define DK     64

// ---------------- static device scratch (no allocations allowed) ----------------
__device__ float gQ[NB*NHEAD*NPOS*DK];   // 33.5 MB  [b,h,n,dk]
__device__ float gK[NB*NHEAD*NPOS*DK];
__device__ float gV[NB*NHEAD*NPOS*DK];
__device__ float gO[NB*DMODEL*NPOS];     // attention out, image layout
__device__ float gZ[NB*DMODEL*NPOS];     // post Wo+InstanceNorm

// Split a loaded fp32 fragment into tf32 hi + tf32 lo (3xTF32 trick).
template <typename FragT>
__device__ __forceinline__ void split_frag(FragT& hi, FragT& lo) {
#pragma unroll
    for (int t = 0; t < hi.num_elements; t++) {
        float v = hi.x[t];
        float h = wmma::__float_to_tf32(v);
        hi.x[t] = h;
        lo.x[t] = wmma::__float_to_tf32(v - h);
    }
}

// =====================================================================
// Shared GEMM body: C(64x128) = W(64x512 slice) @ X(512 x 128 slice) + bias
// 3xTF32, double-buffered k-tiles (BK=32). 256 threads.
// sbuf must hold 13824 floats: As[2][64*40] | Bs[2][32*136]; epilogue
// reuses the front as Cs[64][136].
// =====================================================================
__device__ __forceinline__ void gemm_body(
    const float* __restrict__ Xb, const float* __restrict__ W,
    float* __restrict__ sbuf, int m0, int n0,
    wmma::fragment<wmma::accumulator,16,16,8,float> (&c)[2][2],
    int wm, int wn)
{
    float* As = sbuf;                 // [2][2560]
    float* Bs = sbuf + 2*2560;        // [2][4352]
    const int tid = threadIdx.x;

#pragma unroll
    for (int i=0;i<2;i++)
#pragma unroll
        for (int j=0;j<2;j++) wmma::fill_fragment(c[i][j], 0.0f);

    // prologue load of k-tile 0 into buffer 0
    {
#pragma unroll
        for (int i=0;i<2;i++){
            int idx = tid + i*256, r = idx>>3, c4 = idx&7;
            *(float4*)(As + r*40 + c4*4) =
                *(const float4*)(W + (size_t)(m0+r)*DMODEL + c4*4);
        }
#pragma unroll
        for (int i=0;i<4;i++){
            int idx = tid + i*256, r = idx>>5, c4 = idx&31;
            *(float4*)(Bs + r*136 + c4*4) =
                *(const float4*)(Xb + (size_t)r*NPOS + n0 + c4*4);
        }
    }
    __syncthreads();

    for (int k0 = 0; k0 < DMODEL; k0 += 32) {
        const int cur = (k0 >> 5) & 1;
        if (k0 + 32 < DMODEL) {
            const int nxt = cur ^ 1;
#pragma unroll
            for (int i=0;i<2;i++){
                int idx = tid + i*256, r = idx>>3, c4 = idx&7;
                *(float4*)(As + nxt*2560 + r*40 + c4*4) =
                    *(const float4*)(W + (size_t)(m0+r)*DMODEL + (k0+32) + c4*4);
            }
#pragma unroll
            for (int i=0;i<4;i++){
                int idx = tid + i*256, r = idx>>5, c4 = idx&31;
                *(float4*)(Bs + nxt*4352 + r*136 + c4*4) =
                    *(const float4*)(Xb + (size_t)(k0+32+r)*NPOS + n0 + c4*4);
            }
        }
        const float* Ac = As + cur*2560;
        const float* Bc = Bs + cur*4352;
#pragma unroll
        for (int kk=0;kk<32;kk+=8){
            wmma::fragment<wmma::matrix_a,16,16,8,wmma::precision::tf32,wmma::row_major> ah[2], al[2];
            wmma::fragment<wmma::matrix_b,16,16,8,wmma::precision::tf32,wmma::row_major> bh[2], bl[2];
#pragma unroll
            for (int i=0;i<2;i++){
                wmma::load_matrix_sync(ah[i], Ac + (wm*32+i*16)*40 + kk, 40);
                split_frag(ah[i], al[i]);
            }
#pragma unroll
            for (int j=0;j<2;j++){
                wmma::load_matrix_sync(bh[j], Bc + kk*136 + wn*32 + j*16, 136);
                split_frag(bh[j], bl[j]);
            }
#pragma unroll
            for (int i=0;i<2;i++)
#pragma unroll
                for (int j=0;j<2;j++){
                    wmma::mma_sync(c[i][j], al[i], bh[j], c[i][j]);
                    wmma::mma_sync(c[i][j], ah[i], bl[j], c[i][j]);
                    wmma::mma_sync(c[i][j], ah[i], bh[j], c[i][j]);
                }
        }
        __syncthreads();
    }
}

// ---- plain GEMM (used for both Wo convs): out[b][o][p] = W@X + bias ----
__global__ __launch_bounds__(256) void gemm_k(
    const float* __restrict__ X, const float* __restrict__ W,
    const float* __restrict__ bias, float* __restrict__ out)
{
    __shared__ __align__(16) float sbuf[13824];   // 55.3 KB
    const int b  = blockIdx.z;
    const int m0 = blockIdx.y * 64;
    const int n0 = blockIdx.x * 128;
    const int tid = threadIdx.x;
    const int wid = tid >> 5;
    const int wm  = wid & 1;
    const int wn  = wid >> 1;

    wmma::fragment<wmma::accumulator,16,16,8,float> c[2][2];
    gemm_body(X + (size_t)b*DMODEL*NPOS, W, sbuf, m0, n0, c, wm, wn);

    float* Cs = sbuf;
#pragma unroll
    for (int i=0;i<2;i++)
#pragma unroll
        for (int j=0;j<2;j++)
            wmma::store_matrix_sync(Cs + (wm*32+i*16)*136 + wn*32 + j*16,
                                    c[i][j], 136, wmma::mem_row_major);
    __syncthreads();

    float* ob = out + (size_t)b*DMODEL*NPOS;
    for (int idx = tid; idx < 64*128; idx += 256) {
        int r = idx >> 7, cc = idx & 127;
        int o = m0 + r, p = n0 + cc;
        ob[(size_t)o*NPOS + p] = Cs[r*136+cc] + bias[o];
    }
}

// ---- fused QKV GEMM: z = mat*16 + b; gather epilogue to [b,h,n,dk] ----
__global__ __launch_bounds__(256) void gemm_qkv(
    const float* __restrict__ X,
    const float* __restrict__ Wq, const float* __restrict__ Wk, const float* __restrict__ Wv,
    const float* __restrict__ bq, const float* __restrict__ bk, const float* __restrict__ bv,
    float* __restrict__ outQ, float* __restrict__ outK, float* __restrict__ outV)
{
    __shared__ __align__(16) float sbuf[13824];
    const int z   = blockIdx.z;
    const int b   = z & 15;
    const int mat = z >> 4;
    const float* W    = (mat==0) ? Wq : (mat==1) ? Wk : Wv;
    const float* bias = (mat==0) ? bq : (mat==1) ? bk : bv;
    float* out        = (mat==0) ? outQ : (mat==1) ? outK : outV;

    const int m0 = blockIdx.y * 64;
    const int n0 = blockIdx.x * 128;
    const int tid = threadIdx.x;
    const int wid = tid >> 5;
    const int wm  = wid & 1;
    const int wn  = wid >> 1;

    wmma::fragment<wmma::accumulator,16,16,8,float> c[2][2];
    gemm_body(X + (size_t)b*DMODEL*NPOS, W, sbuf, m0, n0, c, wm, wn);

    float* Cs = sbuf;
#pragma unroll
    for (int i=0;i<2;i++)
#pragma unroll
        for (int j=0;j<2;j++)
            wmma::store_matrix_sync(Cs + (wm*32+i*16)*136 + wn*32 + j*16,
                                    c[i][j], 136, wmma::mem_row_major);
    __syncthreads();

    for (int idx = tid; idx < 64*128; idx += 256) {
        int r = idx >> 7, cc = idx & 127;
        int o = m0 + r, p = n0 + cc;
        int h  = (p & 511) >> 6;
        int n  = 2*o + (p >> 9);
        int dk = p & 63;
        out[(((size_t)b*NHEAD + h)*NPOS + n)*DK + dk] = Cs[r*136+cc] + bias[o];
    }
}

// =====================================================================
// Fused attention v2: 512 threads (16 warps), double-buffered K/V chunks.
//   S phase : 16 warp tiles (2m x 8n of 16x16) per 32x128 chunk, 3xTF32.
//   softmax : warp per row, 2 sweeps of 16 rows.
//   PV phase: split-K — 2 groups x 8 tiles; each group covers half the
//             kk range of every chunk; smem reduction in epilogue.
// smem: Ss 32x1032 | Qs 32x72 | KV[2] 128x72  = 215,040 B (1 CTA/SM).
// =====================================================================
#define S_LD   1032
#define QKV_LD 72
#define ATTN_SMEM_FLOATS (32*S_LD + 32*QKV_LD + 2*128*QKV_LD)

__global__ __launch_bounds__(512) void attn_kernel(
    const float* __restrict__ Q, const float* __restrict__ K,
    const float* __restrict__ V, float* __restrict__ O)
{
    extern __shared__ __align__(16) float smem[];
    float* Ss  = smem;                       // [32][1032]
    float* Qs  = smem + 32*S_LD;             // [32][72]
    float* KV0 = Qs + 32*QKV_LD;             // [128][72]
    float* KV1 = KV0 + 128*QKV_LD;           // [128][72]

    const int bh = blockIdx.y;
    const int b  = bh >> 3, h = bh & 7;
    const int m0 = blockIdx.x * 32;
    const int tid = threadIdx.x;
    const int wid = tid >> 5;                // 0..15
    const int lane = tid & 31;

    const float* Qb = Q + (size_t)bh*NPOS*DK;
    const float* Kb = K + (size_t)bh*NPOS*DK;
    const float* Vb = V + (size_t)bh*NPOS*DK;

    // ---- load Q tile (512 float4, one per thread) + prefetch K chunk 0 ----
    {
        int r = tid >> 4, c4 = tid & 15;
        *(float4*)(Qs + r*QKV_LD + c4*4) =
            *(const float4*)(Qb + (size_t)(m0+r)*DK + c4*4);
    }
#pragma unroll
    for (int i=0;i<4;i++){
        int idx = tid + i*512;
        int r = idx >> 4, c4 = idx & 15;
        *(float4*)(KV0 + r*QKV_LD + c4*4) =
            *(const float4*)(Kb + (size_t)r*DK + c4*4);
    }
    __syncthreads();

    // ---- S phase: 8 key chunks of 128, double buffered ----
    {
        const int wm = wid & 1;      // 2 stripes of 16 rows
        const int wn = wid >> 1;     // 8 stripes of 16 cols
        for (int kc = 0; kc < 8; kc++) {
            float* cur = (kc & 1) ? KV1 : KV0;
            float* nxt = (kc & 1) ? KV0 : KV1;
            if (kc < 7) {
#pragma unroll
                for (int i=0;i<4;i++){
                    int idx = tid + i*512;
                    int r = idx >> 4, c4 = idx & 15;
                    *(float4*)(nxt + r*QKV_LD + c4*4) =
                        *(const float4*)(Kb + (size_t)((kc+1)*128+r)*DK + c4*4);
                }
            }
            wmma::fragment<wmma::accumulator,16,16,8,float> acc;
            wmma::fill_fragment(acc, 0.0f);
#pragma unroll
            for (int kk=0;kk<64;kk+=8){
                wmma::fragment<wmma::matrix_a,16,16,8,wmma::precision::tf32,wmma::row_major> ah, al;
                wmma::load_matrix_sync(ah, Qs + (wm*16)*QKV_LD + kk, QKV_LD);
                split_frag(ah, al);
                wmma::fragment<wmma::matrix_b,16,16,8,wmma::precision::tf32,wmma::col_major> bh2, bl2;
                wmma::load_matrix_sync(bh2, cur + (wn*16)*QKV_LD + kk, QKV_LD);
                split_frag(bh2, bl2);
                wmma::mma_sync(acc, al, bh2, acc);
                wmma::mma_sync(acc, ah, bl2, acc);
                wmma::mma_sync(acc, ah, bh2, acc);
            }
#pragma unroll
            for (int t=0;t<acc.num_elements;t++) acc.x[t] *= 0.125f;
            wmma::store_matrix_sync(Ss + (wm*16)*S_LD + kc*128 + wn*16,
                                    acc, S_LD, wmma::mem_row_major);
            __syncthreads();
        }
    }

    // ---- prefetch V chunk 0 (K data dead), overlapping the softmax ----
#pragma unroll
    for (int i=0;i<4;i++){
        int idx = tid + i*512;
        int r = idx >> 4, c4 = idx & 15;
        *(float4*)(KV0 + r*QKV_LD + c4*4) =
            *(const float4*)(Vb + (size_t)r*DK + c4*4);
    }

    // ---- softmax: warp per row, 2 sweeps of 16 rows ----
#pragma unroll
    for (int it=0; it<2; it++){
        int r = it*16 + wid;
        float4* p = (float4*)(Ss + (size_t)r*S_LD);
        float4 v[8];
        float mx = -1e30f;
#pragma unroll
        for (int i=0;i<8;i++){
            v[i] = p[lane + 32*i];
            mx = fmaxf(mx, fmaxf(fmaxf(v[i].x, v[i].y), fmaxf(v[i].z, v[i].w)));
        }
#pragma unroll
        for (int s=16;s>0;s>>=1) mx = fmaxf(mx, __shfl_xor_sync(0xffffffffu, mx, s));
        float sum = 0.0f;
#pragma unroll
        for (int i=0;i<8;i++){
            v[i].x = __expf(v[i].x - mx); v[i].y = __expf(v[i].y - mx);
            v[i].z = __expf(v[i].z - mx); v[i].w = __expf(v[i].w - mx);
            sum += v[i].x + v[i].y + v[i].z + v[i].w;
        }
#pragma unroll
        for (int s=16;s>0;s>>=1) sum += __shfl_xor_sync(0xffffffffu, sum, s);
        float inv = 1.0f / sum;
#pragma unroll
        for (int i=0;i<8;i++){
            v[i].x *= inv; v[i].y *= inv; v[i].z *= inv; v[i].w *= inv;
            p[lane + 32*i] = v[i];
        }
    }
    __syncthreads();

    // ---- PV phase: split-K over 2 groups; 8 tiles (2m x 4dk) per group ----
    const int grp = wid >> 3;        // 0: kk 0..63, 1: kk 64..127 of each chunk
    const int w8  = wid & 7;
    const int om  = w8 & 1;          // 2 stripes of 16 rows
    const int on  = w8 >> 1;         // 4 stripes of 16 dk cols
    wmma::fragment<wmma::accumulator,16,16,8,float> oacc;
    wmma::fill_fragment(oacc, 0.0f);

    for (int vc = 0; vc < 8; vc++) {
        float* cur = (vc & 1) ? KV1 : KV0;
        float* nxt = (vc & 1) ? KV0 : KV1;
        if (vc < 7) {
#pragma unroll
            for (int i=0;i<4;i++){
                int idx = tid + i*512;
                int r = idx >> 4, c4 = idx & 15;
                *(float4*)(nxt + r*QKV_LD + c4*4) =
                    *(const float4*)(Vb + (size_t)((vc+1)*128+r)*DK + c4*4);
            }
        }
#pragma unroll
        for (int k8=0;k8<8;k8++){
            int kk = grp*64 + k8*8;
            wmma::fragment<wmma::matrix_a,16,16,8,wmma::precision::tf32,wmma::row_major> ah, al;
            wmma::load_matrix_sync(ah, Ss + (om*16)*S_LD + vc*128 + kk, S_LD);
            split_frag(ah, al);
            wmma::fragment<wmma::matrix_b,16,16,8,wmma::precision::tf32,wmma::row_major> bh2, bl2;
            wmma::load_matrix_sync(bh2, cur + kk*QKV_LD + on*16, QKV_LD);
            split_frag(bh2, bl2);
            wmma::mma_sync(oacc, al, bh2, oacc);
            wmma::mma_sync(oacc, ah, bl2, oacc);
            wmma::mma_sync(oacc, ah, bh2, oacc);
        }
        __syncthreads();
    }

    // ---- epilogue: both groups stage col-major [dk][m], sum, image write ----
    float* Ca = Ss;            // 64 x 40
    float* Cb = Ss + 64*40;    // 64 x 40
    wmma::store_matrix_sync((grp ? Cb : Ca) + (on*16)*40 + om*16,
                            oacc, 40, wmma::mem_col_major);
    __syncthreads();

    float* Ob = O + (size_t)b*DMODEL*NPOS;
    for (int idx = tid; idx < 64*32; idx += 512) {
        int dk = idx >> 5, mm = idx & 31;
        Ob[(size_t)(h*DK + dk)*NPOS + m0 + mm] = Ca[dk*40 + mm] + Cb[dk*40 + mm];
    }
}

// =====================================================================
// InstanceNorm (affine=False, biased var, eps=1e-5) in place.
// One warp per (b,c) row of 1024 spatial values; two-pass in registers.
// =====================================================================
__global__ __launch_bounds__(256) void inorm_kernel(float* __restrict__ Z)
{
    const int row  = blockIdx.x*8 + (threadIdx.x >> 5);
    const int lane = threadIdx.x & 31;
    float4* p = (float4*)(Z + (size_t)row*NPOS);
    float4 v[8];
    float s = 0.0f;
#pragma unroll
    for (int i=0;i<8;i++){ v[i] = p[lane + 32*i]; s += v[i].x+v[i].y+v[i].z+v[i].w; }
#pragma unroll
    for (int sh=16;sh>0;sh>>=1) s += __shfl_xor_sync(0xffffffffu, s, sh);
    const float mean = s * (1.0f/1024.0f);
    float q = 0.0f;
#pragma unroll
    for (int i=0;i<8;i++){
        float a=v[i].x-mean, b2=v[i].y-mean, c2=v[i].z-mean, d=v[i].w-mean;
        q += a*a + b2*b2 + c2*c2 + d*d;
    }
#pragma unroll
    for (int sh=16;sh>0;sh>>=1) q += __shfl_xor_sync(0xffffffffu, q, sh);
    const float inv = rsqrtf(q * (1.0f/1024.0f) + 1e-5f);
#pragma unroll
    for (int i=0;i<8;i++){
        v[i].x = (v[i].x-mean)*inv; v[i].y = (v[i].y-mean)*inv;
        v[i].z = (v[i].z-mean)*inv; v[i].w = (v[i].w-mean)*inv;
        p[lane + 32*i] = v[i];
    }
}

// =====================================================================
extern "C" void kernel_launch(void* const* d_in, const int* in_sizes, int n_in,
                              void* d_out, int out_size)
{
    (void)in_sizes; (void)n_in; (void)out_size;
    const float* x  = (const float*)d_in[0];
    const float* Wq = (const float*)d_in[1];
    const float* bq = (const float*)d_in[2];
    const float* Wk = (const float*)d_in[3];
    const float* bk = (const float*)d_in[4];
    const float* Wv = (const float*)d_in[5];
    const float* bv = (const float*)d_in[6];
    const float* Wo = (const float*)d_in[7];
    const float* bo = (const float*)d_in[8];
    float* out = (float*)d_out;

    float *pQ, *pK, *pV, *pO, *pZ;
    cudaGetSymbolAddress((void**)&pQ, gQ);
    cudaGetSymbolAddress((void**)&pK, gK);
    cudaGetSymbolAddress((void**)&pV, gV);
    cudaGetSymbolAddress((void**)&pO, gO);
    cudaGetSymbolAddress((void**)&pZ, gZ);

    const int attn_smem = ATTN_SMEM_FLOATS * (int)sizeof(float);   // 215,040 B
    cudaFuncSetAttribute(attn_kernel,
                         cudaFuncAttributeMaxDynamicSharedMemorySize, attn_smem);

    dim3 gGemm(8, 8, 16);          // n-tiles, m-tiles, batch
    dim3 gQKV (8, 8, 48);          // n-tiles, m-tiles, batch*3

    gemm_qkv<<<gQKV, 256>>>(x, Wq, Wk, Wv, bq, bk, bv, pQ, pK, pV);

    attn_kernel<<<dim3(32, 128), 512, attn_smem>>>(pQ, pK, pV, pO);

    gemm_k<<<gGemm, 256>>>(pO, Wo, bo, pZ);
    inorm_kernel<<<1024, 256>>>(pZ);           // 8192 rows / 8 per block
    gemm_k<<<gGemm, 256>>>(pZ, Wo, bo, out);
}

// round 16
// speedup vs baseline: 2.1403x; 2.1337x over previous
#include <cuda_runtime.h>
#include <cuda_bf16.h>
#include <mma.h>
#include <cstdint>

using namespace nvcuda;

#define NB     16
#define DMODEL 512
#define NPOS   1024
#define NHEAD  8
#define DK     64

// ---------------- static device scratch (no allocations allowed) ----------------
__device__ float gQ[NB*NHEAD*NPOS*DK];   // [b,h,n,dk]
__device__ float gK[NB*NHEAD*NPOS*DK];
__device__ float gV[NB*NHEAD*NPOS*DK];
__device__ float gO[NB*DMODEL*NPOS];     // attention out, image layout
__device__ float gZ[NB*DMODEL*NPOS];     // post Wo+InstanceNorm

typedef wmma::fragment<wmma::matrix_a,16,16,16,__nv_bfloat16,wmma::row_major> FragA;
typedef wmma::fragment<wmma::matrix_b,16,16,16,__nv_bfloat16,wmma::row_major> FragBr;
typedef wmma::fragment<wmma::matrix_b,16,16,16,__nv_bfloat16,wmma::col_major> FragBc;
typedef wmma::fragment<wmma::accumulator,16,16,16,float> FragC;

// Split 4 fp32 into bf16 hi/lo planes, packed 8B stores. ph/pl must be 8B aligned.
__device__ __forceinline__ void bsplit4(float4 f, __nv_bfloat16* ph, __nv_bfloat16* pl)
{
    float fr[4] = {f.x, f.y, f.z, f.w};
    unsigned short hb[4], lb[4];
#pragma unroll
    for (int i=0;i<4;i++){
        __nv_bfloat16 h = __float2bfloat16(fr[i]);
        __nv_bfloat16 l = __float2bfloat16(fr[i] - __bfloat162float(h));
        hb[i] = *(unsigned short*)&h;
        lb[i] = *(unsigned short*)&l;
    }
    *(ushort4*)ph = make_ushort4(hb[0],hb[1],hb[2],hb[3]);
    *(ushort4*)pl = make_ushort4(lb[0],lb[1],lb[2],lb[3]);
}

// =====================================================================
// GEMM body: C(64x128) = W(64x512) @ X(512x128 slice), 3x-BF16, k16 MMA,
// double-buffered BK=32 tiles. 256 threads.
// smem: Ash[2][64*40] Asl[2] Bsh[2][32*136] Bsl[2]  (bf16) = 55,296 B
// =====================================================================
#define GEMM_SMEM_BYTES 55296

__device__ __forceinline__ void gemm_body(
    const float* __restrict__ Xb, const float* __restrict__ W,
    char* __restrict__ sbuf, int m0, int n0,
    FragC (&c)[2][2], int wm, int wn)
{
    __nv_bfloat16* Ash = (__nv_bfloat16*)sbuf;   // [2][2560]
    __nv_bfloat16* Asl = Ash + 2*2560;
    __nv_bfloat16* Bsh = Asl + 2*2560;           // [2][4352]
    __nv_bfloat16* Bsl = Bsh + 2*4352;
    const int tid = threadIdx.x;

#pragma unroll
    for (int i=0;i<2;i++)
#pragma unroll
        for (int j=0;j<2;j++) wmma::fill_fragment(c[i][j], 0.0f);

    // prologue: k-tile 0 -> buffer 0
#pragma unroll
    for (int i=0;i<2;i++){
        int idx = tid + i*256, r = idx>>3, c4 = idx&7;
        bsplit4(*(const float4*)(W + (size_t)(m0+r)*DMODEL + c4*4),
                Ash + r*40 + c4*4, Asl + r*40 + c4*4);
    }
#pragma unroll
    for (int i=0;i<4;i++){
        int idx = tid + i*256, r = idx>>5, c4 = idx&31;
        bsplit4(*(const float4*)(Xb + (size_t)r*NPOS + n0 + c4*4),
                Bsh + r*136 + c4*4, Bsl + r*136 + c4*4);
    }
    __syncthreads();

    for (int k0 = 0; k0 < DMODEL; k0 += 32) {
        const int cur = (k0 >> 5) & 1;
        if (k0 + 32 < DMODEL) {
            const int nxt = cur ^ 1;
#pragma unroll
            for (int i=0;i<2;i++){
                int idx = tid + i*256, r = idx>>3, c4 = idx&7;
                bsplit4(*(const float4*)(W + (size_t)(m0+r)*DMODEL + (k0+32) + c4*4),
                        Ash + nxt*2560 + r*40 + c4*4, Asl + nxt*2560 + r*40 + c4*4);
            }
#pragma unroll
            for (int i=0;i<4;i++){
                int idx = tid + i*256, r = idx>>5, c4 = idx&31;
                bsplit4(*(const float4*)(Xb + (size_t)(k0+32+r)*NPOS + n0 + c4*4),
                        Bsh + nxt*4352 + r*136 + c4*4, Bsl + nxt*4352 + r*136 + c4*4);
            }
        }
        const __nv_bfloat16* Ah = Ash + cur*2560;
        const __nv_bfloat16* Al = Asl + cur*2560;
        const __nv_bfloat16* Bh = Bsh + cur*4352;
        const __nv_bfloat16* Bl = Bsl + cur*4352;
#pragma unroll
        for (int kk=0;kk<32;kk+=16){
            FragA ah[2], al[2];
            FragBr bh[2], bl[2];
#pragma unroll
            for (int i=0;i<2;i++){
                wmma::load_matrix_sync(ah[i], Ah + (wm*32+i*16)*40 + kk, 40);
                wmma::load_matrix_sync(al[i], Al + (wm*32+i*16)*40 + kk, 40);
            }
#pragma unroll
            for (int j=0;j<2;j++){
                wmma::load_matrix_sync(bh[j], Bh + kk*136 + wn*32 + j*16, 136);
                wmma::load_matrix_sync(bl[j], Bl + kk*136 + wn*32 + j*16, 136);
            }
#pragma unroll
            for (int i=0;i<2;i++)
#pragma unroll
                for (int j=0;j<2;j++){
                    wmma::mma_sync(c[i][j], al[i], bh[j], c[i][j]);
                    wmma::mma_sync(c[i][j], ah[i], bl[j], c[i][j]);
                    wmma::mma_sync(c[i][j], ah[i], bh[j], c[i][j]);
                }
        }
        __syncthreads();
    }
}

// ---- plain GEMM (both Wo convs): out[b][o][p] = W@X + bias ----
__global__ __launch_bounds__(256) void gemm_k(
    const float* __restrict__ X, const float* __restrict__ W,
    const float* __restrict__ bias, float* __restrict__ out)
{
    __shared__ __align__(16) char sbuf[GEMM_SMEM_BYTES];
    const int b  = blockIdx.z;
    const int m0 = blockIdx.y * 64;
    const int n0 = blockIdx.x * 128;
    const int tid = threadIdx.x;
    const int wid = tid >> 5;
    const int wm  = wid & 1;
    const int wn  = wid >> 1;

    FragC c[2][2];
    gemm_body(X + (size_t)b*DMODEL*NPOS, W, sbuf, m0, n0, c, wm, wn);

    float* Cs = (float*)sbuf;    // [64][136]
#pragma unroll
    for (int i=0;i<2;i++)
#pragma unroll
        for (int j=0;j<2;j++)
            wmma::store_matrix_sync(Cs + (wm*32+i*16)*136 + wn*32 + j*16,
                                    c[i][j], 136, wmma::mem_row_major);
    __syncthreads();

    float* ob = out + (size_t)b*DMODEL*NPOS;
    for (int idx = tid; idx < 64*128; idx += 256) {
        int r = idx >> 7, cc = idx & 127;
        int o = m0 + r, p = n0 + cc;
        ob[(size_t)o*NPOS + p] = Cs[r*136+cc] + bias[o];
    }
}

// ---- fused QKV GEMM with gather epilogue to [b,h,n,dk] ----
__global__ __launch_bounds__(256) void gemm_qkv(
    const float* __restrict__ X,
    const float* __restrict__ Wq, const float* __restrict__ Wk, const float* __restrict__ Wv,
    const float* __restrict__ bq, const float* __restrict__ bk, const float* __restrict__ bv,
    float* __restrict__ outQ, float* __restrict__ outK, float* __restrict__ outV)
{
    __shared__ __align__(16) char sbuf[GEMM_SMEM_BYTES];
    const int z   = blockIdx.z;
    const int b   = z & 15;
    const int mat = z >> 4;
    const float* W    = (mat==0) ? Wq : (mat==1) ? Wk : Wv;
    const float* bias = (mat==0) ? bq : (mat==1) ? bk : bv;
    float* out        = (mat==0) ? outQ : (mat==1) ? outK : outV;

    const int m0 = blockIdx.y * 64;
    const int n0 = blockIdx.x * 128;
    const int tid = threadIdx.x;
    const int wid = tid >> 5;
    const int wm  = wid & 1;
    const int wn  = wid >> 1;

    FragC c[2][2];
    gemm_body(X + (size_t)b*DMODEL*NPOS, W, sbuf, m0, n0, c, wm, wn);

    float* Cs = (float*)sbuf;
#pragma unroll
    for (int i=0;i<2;i++)
#pragma unroll
        for (int j=0;j<2;j++)
            wmma::store_matrix_sync(Cs + (wm*32+i*16)*136 + wn*32 + j*16,
                                    c[i][j], 136, wmma::mem_row_major);
    __syncthreads();

    for (int idx = tid; idx < 64*128; idx += 256) {
        int r = idx >> 7, cc = idx & 127;
        int o = m0 + r, p = n0 + cc;
        int h  = (p & 511) >> 6;
        int n  = 2*o + (p >> 9);
        int dk = p & 63;
        out[(((size_t)b*NHEAD + h)*NPOS + n)*DK + dk] = Cs[r*136+cc] + bias[o];
    }
}

// =====================================================================
// Fused attention, 3x-BF16, 512 threads, double-buffered K/V chunks.
//   S phase : 16 warp tiles (2m x 8n) per 32x128 chunk.
//   softmax : warp per row; writes P back as bf16 hi/lo planes overlaid
//             row-for-row on the fp32 S stripe (4128 B/row = 2064h+2064l).
//   PV phase: split-K, 2 groups x (2m x 4dk) tiles; smem reduction.
// smem: Ss 32x1032 fp32 (132,096) | Qh/Ql 32x72 bf16 (9,216)
//       | KV hi/lo x2 bufs 128x72 bf16 (73,728)  = 215,040 B
// =====================================================================
#define S_LD   1032
#define PH_LD  2064        // bf16 elements; = one 4128B fp32 row
#define KV_LD  72
#define ATTN_SMEM_BYTES (32*S_LD*4 + 2*32*KV_LD*2 + 4*128*KV_LD*2)

__global__ __launch_bounds__(512) void attn_kernel(
    const float* __restrict__ Q, const float* __restrict__ K,
    const float* __restrict__ V, float* __restrict__ O)
{
    extern __shared__ __align__(16) char smem[];
    float* Ss = (float*)smem;                               // [32][1032] fp32
    __nv_bfloat16* Qh  = (__nv_bfloat16*)(smem + 32*S_LD*4);    // [32][72]
    __nv_bfloat16* Ql  = Qh + 32*KV_LD;
    __nv_bfloat16* KVh0 = Ql + 32*KV_LD;                    // [128][72]
    __nv_bfloat16* KVl0 = KVh0 + 128*KV_LD;
    __nv_bfloat16* KVh1 = KVl0 + 128*KV_LD;
    __nv_bfloat16* KVl1 = KVh1 + 128*KV_LD;
    __nv_bfloat16* Pall = (__nv_bfloat16*)smem;             // hi at row*PH_LD, lo +1032

    const int bh = blockIdx.y;
    const int b  = bh >> 3, h = bh & 7;
    const int m0 = blockIdx.x * 32;
    const int tid = threadIdx.x;
    const int wid = tid >> 5;                // 0..15
    const int lane = tid & 31;

    const float* Qb = Q + (size_t)bh*NPOS*DK;
    const float* Kb = K + (size_t)bh*NPOS*DK;
    const float* Vb = V + (size_t)bh*NPOS*DK;

    // ---- Q tile (512 float4) + prefetch K chunk 0 ----
    {
        int r = tid >> 4, c4 = tid & 15;
        bsplit4(*(const float4*)(Qb + (size_t)(m0+r)*DK + c4*4),
                Qh + r*KV_LD + c4*4, Ql + r*KV_LD + c4*4);
    }
#pragma unroll
    for (int i=0;i<4;i++){
        int idx = tid + i*512, r = idx >> 4, c4 = idx & 15;
        bsplit4(*(const float4*)(Kb + (size_t)r*DK + c4*4),
                KVh0 + r*KV_LD + c4*4, KVl0 + r*KV_LD + c4*4);
    }
    __syncthreads();

    // ---- S phase: 8 key chunks of 128, double buffered ----
    {
        const int wm = wid & 1;      // 2 stripes of 16 rows
        const int wn = wid >> 1;     // 8 stripes of 16 cols
        for (int kc = 0; kc < 8; kc++) {
            const __nv_bfloat16* ch = (kc & 1) ? KVh1 : KVh0;
            const __nv_bfloat16* cl = (kc & 1) ? KVl1 : KVl0;
            __nv_bfloat16* nh = (kc & 1) ? KVh0 : KVh1;
            __nv_bfloat16* nl = (kc & 1) ? KVl0 : KVl1;
            if (kc < 7) {
#pragma unroll
                for (int i=0;i<4;i++){
                    int idx = tid + i*512, r = idx >> 4, c4 = idx & 15;
                    bsplit4(*(const float4*)(Kb + (size_t)((kc+1)*128+r)*DK + c4*4),
                            nh + r*KV_LD + c4*4, nl + r*KV_LD + c4*4);
                }
            }
            FragC acc;
            wmma::fill_fragment(acc, 0.0f);
#pragma unroll
            for (int kk=0;kk<64;kk+=16){
                FragA ah, al;
                wmma::load_matrix_sync(ah, Qh + (wm*16)*KV_LD + kk, KV_LD);
                wmma::load_matrix_sync(al, Ql + (wm*16)*KV_LD + kk, KV_LD);
                FragBc bh2, bl2;
                wmma::load_matrix_sync(bh2, ch + (wn*16)*KV_LD + kk, KV_LD);
                wmma::load_matrix_sync(bl2, cl + (wn*16)*KV_LD + kk, KV_LD);
                wmma::mma_sync(acc, al, bh2, acc);
                wmma::mma_sync(acc, ah, bl2, acc);
                wmma::mma_sync(acc, ah, bh2, acc);
            }
#pragma unroll
            for (int t=0;t<acc.num_elements;t++) acc.x[t] *= 0.125f;
            wmma::store_matrix_sync(Ss + (wm*16)*S_LD + kc*128 + wn*16,
                                    acc, S_LD, wmma::mem_row_major);
            __syncthreads();
        }
    }

    // ---- prefetch V chunk 0 (K data dead), overlapping softmax ----
#pragma unroll
    for (int i=0;i<4;i++){
        int idx = tid + i*512, r = idx >> 4, c4 = idx & 15;
        bsplit4(*(const float4*)(Vb + (size_t)r*DK + c4*4),
                KVh0 + r*KV_LD + c4*4, KVl0 + r*KV_LD + c4*4);
    }

    // ---- softmax: warp per row; write back P as bf16 hi/lo in-place ----
#pragma unroll
    for (int it=0; it<2; it++){
        int r = it*16 + wid;
        float4* p = (float4*)(Ss + (size_t)r*S_LD);
        float4 v[8];
        float mx = -1e30f;
#pragma unroll
        for (int i=0;i<8;i++){
            v[i] = p[lane + 32*i];
            mx = fmaxf(mx, fmaxf(fmaxf(v[i].x, v[i].y), fmaxf(v[i].z, v[i].w)));
        }
#pragma unroll
        for (int s=16;s>0;s>>=1) mx = fmaxf(mx, __shfl_xor_sync(0xffffffffu, mx, s));
        float sum = 0.0f;
#pragma unroll
        for (int i=0;i<8;i++){
            v[i].x = __expf(v[i].x - mx); v[i].y = __expf(v[i].y - mx);
            v[i].z = __expf(v[i].z - mx); v[i].w = __expf(v[i].w - mx);
            sum += v[i].x + v[i].y + v[i].z + v[i].w;
        }
#pragma unroll
        for (int s=16;s>0;s>>=1) sum += __shfl_xor_sync(0xffffffffu, sum, s);
        float inv = 1.0f / sum;
        __nv_bfloat16* ph = Pall + (size_t)r*PH_LD;
        __nv_bfloat16* pl = ph + 1032;
#pragma unroll
        for (int i=0;i<8;i++){
            float4 w4 = make_float4(v[i].x*inv, v[i].y*inv, v[i].z*inv, v[i].w*inv);
            bsplit4(w4, ph + (lane+32*i)*4, pl + (lane+32*i)*4);
        }
    }
    __syncthreads();

    // ---- PV phase: split-K, 2 groups; 8 tiles (2m x 4dk) per group ----
    const int grp = wid >> 3;        // group 0: kk 0..63, group 1: kk 64..127
    const int w8  = wid & 7;
    const int om  = w8 & 1;          // 2 stripes of 16 rows
    const int on  = w8 >> 1;         // 4 stripes of 16 dk cols
    FragC oacc;
    wmma::fill_fragment(oacc, 0.0f);

    for (int vc = 0; vc < 8; vc++) {
        const __nv_bfloat16* ch = (vc & 1) ? KVh1 : KVh0;
        const __nv_bfloat16* cl = (vc & 1) ? KVl1 : KVl0;
        __nv_bfloat16* nh = (vc & 1) ? KVh0 : KVh1;
        __nv_bfloat16* nl = (vc & 1) ? KVl0 : KVl1;
        if (vc < 7) {
#pragma unroll
            for (int i=0;i<4;i++){
                int idx = tid + i*512, r = idx >> 4, c4 = idx & 15;
                bsplit4(*(const float4*)(Vb + (size_t)((vc+1)*128+r)*DK + c4*4),
                        nh + r*KV_LD + c4*4, nl + r*KV_LD + c4*4);
            }
        }
#pragma unroll
        for (int k8=0;k8<4;k8++){
            int kk = grp*64 + k8*16;
            FragA ah, al;
            wmma::load_matrix_sync(ah, Pall + (size_t)(om*16)*PH_LD + vc*128 + kk, PH_LD);
            wmma::load_matrix_sync(al, Pall + (size_t)(om*16)*PH_LD + 1032 + vc*128 + kk, PH_LD);
            FragBr bh2, bl2;
            wmma::load_matrix_sync(bh2, ch + kk*KV_LD + on*16, KV_LD);
            wmma::load_matrix_sync(bl2, cl + kk*KV_LD + on*16, KV_LD);
            wmma::mma_sync(oacc, al, bh2, oacc);
            wmma::mma_sync(oacc, ah, bl2, oacc);
            wmma::mma_sync(oacc, ah, bh2, oacc);
        }
        __syncthreads();
    }

    // ---- epilogue: both groups stage col-major [dk][m], sum, image write ----
    float* Ca = Ss;            // 64 x 40 fp32 (P data dead)
    float* Cb = Ss + 64*40;
    wmma::store_matrix_sync((grp ? Cb : Ca) + (on*16)*40 + om*16,
                            oacc, 40, wmma::mem_col_major);
    __syncthreads();

    float* Ob = O + (size_t)b*DMODEL*NPOS;
    for (int idx = tid; idx < 64*32; idx += 512) {
        int dk = idx >> 5, mm = idx & 31;
        Ob[(size_t)(h*DK + dk)*NPOS + m0 + mm] = Ca[dk*40 + mm] + Cb[dk*40 + mm];
    }
}

// =====================================================================
// InstanceNorm (affine=False, biased var, eps=1e-5) in place.
// =====================================================================
__global__ __launch_bounds__(256) void inorm_kernel(float* __restrict__ Z)
{
    const int row  = blockIdx.x*8 + (threadIdx.x >> 5);
    const int lane = threadIdx.x & 31;
    float4* p = (float4*)(Z + (size_t)row*NPOS);
    float4 v[8];
    float s = 0.0f;
#pragma unroll
    for (int i=0;i<8;i++){ v[i] = p[lane + 32*i]; s += v[i].x+v[i].y+v[i].z+v[i].w; }
#pragma unroll
    for (int sh=16;sh>0;sh>>=1) s += __shfl_xor_sync(0xffffffffu, s, sh);
    const float mean = s * (1.0f/1024.0f);
    float q = 0.0f;
#pragma unroll
    for (int i=0;i<8;i++){
        float a=v[i].x-mean, b2=v[i].y-mean, c2=v[i].z-mean, d=v[i].w-mean;
        q += a*a + b2*b2 + c2*c2 + d*d;
    }
#pragma unroll
    for (int sh=16;sh>0;sh>>=1) q += __shfl_xor_sync(0xffffffffu, q, sh);
    const float inv = rsqrtf(q * (1.0f/1024.0f) + 1e-5f);
#pragma unroll
    for (int i=0;i<8;i++){
        v[i].x = (v[i].x-mean)*inv; v[i].y = (v[i].y-mean)*inv;
        v[i].z = (v[i].z-mean)*inv; v[i].w = (v[i].w-mean)*inv;
        p[lane + 32*i] = v[i];
    }
}

// =====================================================================
extern "C" void kernel_launch(void* const* d_in, const int* in_sizes, int n_in,
                              void* d_out, int out_size)
{
    (void)in_sizes; (void)n_in; (void)out_size;
    const float* x  = (const float*)d_in[0];
    const float* Wq = (const float*)d_in[1];
    const float* bq = (const float*)d_in[2];
    const float* Wk = (const float*)d_in[3];
    const float* bk = (const float*)d_in[4];
    const float* Wv = (const float*)d_in[5];
    const float* bv = (const float*)d_in[6];
    const float* Wo = (const float*)d_in[7];
    const float* bo = (const float*)d_in[8];
    float* out = (float*)d_out;

    float *pQ, *pK, *pV, *pO, *pZ;
    cudaGetSymbolAddress((void**)&pQ, gQ);
    cudaGetSymbolAddress((void**)&pK, gK);
    cudaGetSymbolAddress((void**)&pV, gV);
    cudaGetSymbolAddress((void**)&pO, gO);
    cudaGetSymbolAddress((void**)&pZ, gZ);

    cudaFuncSetAttribute(attn_kernel,
                         cudaFuncAttributeMaxDynamicSharedMemorySize, ATTN_SMEM_BYTES);

    dim3 gGemm(8, 8, 16);          // n-tiles, m-tiles, batch
    dim3 gQKV (8, 8, 48);          // n-tiles, m-tiles, batch*3

    gemm_qkv<<<gQKV, 256>>>(x, Wq, Wk, Wv, bq, bk, bv, pQ, pK, pV);

    attn_kernel<<<dim3(32, 128), 512, ATTN_SMEM_BYTES>>>(pQ, pK, pV, pO);

    gemm_k<<<gGemm, 256>>>(pO, Wo, bo, pZ);
    inorm_kernel<<<1024, 256>>>(pZ);           // 8192 rows / 8 per block
    gemm_k<<<gGemm, 256>>>(pZ, Wo, bo, out);
}